// round 5
// baseline (speedup 1.0000x reference)
#include <cuda_runtime.h>
#include <cuda_bf16.h>

// Problem constants
#define NN 50000
#define EE 800000
#define FF 16
#define MAXDEG 96   // Poisson(16) degrees; P(deg > 96) astronomically small

// Scratch
__device__ int g_cursor[NN];                      // per-dst edge count / cursor
__device__ int g_el[NN * MAXDEG];                 // bucketed edge ids
__device__ __align__(16) float g_x[4 * NN * FF];  // x = q + agg

// ---------------------------------------------------------------------------
// Kernel 1: zero the cursors (must happen every replay)
// ---------------------------------------------------------------------------
__global__ void k_zcur() {
    int i = blockIdx.x * blockDim.x + threadIdx.x;
    if (i < NN) g_cursor[i] = 0;
}

// ---------------------------------------------------------------------------
// Kernel 2: scatter edge ids into per-dst buckets. 800k int atomics only.
// ---------------------------------------------------------------------------
__global__ void __launch_bounds__(256) k_scatter(const int* __restrict__ ei) {
    int e = blockIdx.x * blockDim.x + threadIdx.x;
    if (e >= EE) return;
    int dst = ei[EE + e];
    int pos = atomicAdd(&g_cursor[dst], 1);
    if (pos < MAXDEG) g_el[dst * MAXDEG + pos] = e;
}

// ---------------------------------------------------------------------------
// Kernel 3: atomic-free gather. Thread = (dst, f4); loops the dst's edge
// bucket with the 4 quaternion components unrolled inside. The 4 f4 lanes
// of each dst share bucket/index loads (L1 broadcast) and read contiguous
// 64B chunks of ea and q. Softmax num/den accumulate in registers.
//   m = q[c,src,f] + ea[c,e,f];  w = exp(beta*m)   (|z| <= ~9: no max pass)
//   x[c,dst,f] = q[c,dst,f] + num/den
// ---------------------------------------------------------------------------
__global__ void __launch_bounds__(256) k_gather(const float* __restrict__ q,
                                                const float* __restrict__ ea,
                                                const int*   __restrict__ ei,
                                                const float* __restrict__ beta) {
    int tid = blockIdx.x * blockDim.x + threadIdx.x;
    if (tid >= NN * 4) return;
    int dst = tid >> 2;
    int f4  = tid & 3;

    float b = beta[0];
    int deg = g_cursor[dst];
    if (deg > MAXDEG) deg = MAXDEG;

    const float4* q4  = (const float4*)q;
    const float4* ea4 = (const float4*)ea;

    float4 num[4], den[4];
#pragma unroll
    for (int c = 0; c < 4; c++) {
        num[c] = make_float4(0.f, 0.f, 0.f, 0.f);
        den[c] = make_float4(0.f, 0.f, 0.f, 0.f);
    }

    int base = dst * MAXDEG;
    int e_pf = (deg > 0) ? g_el[base] : 0;
    int s_pf = (deg > 0) ? __ldg(&ei[e_pf]) : 0;
    for (int i = 0; i < deg; i++) {
        int e   = e_pf;
        int src = s_pf;
        if (i + 1 < deg) {                       // prefetch next entry
            e_pf = g_el[base + i + 1];
            s_pf = __ldg(&ei[e_pf]);
        }
#pragma unroll
        for (int c = 0; c < 4; c++) {
            float4 a  = ea4[(c * EE + e) * 4 + f4];
            float4 qs = q4[(c * NN + src) * 4 + f4];
            float m0 = a.x + qs.x, m1 = a.y + qs.y;
            float m2 = a.z + qs.z, m3 = a.w + qs.w;
            float w0 = __expf(b * m0), w1 = __expf(b * m1);
            float w2 = __expf(b * m2), w3 = __expf(b * m3);
            den[c].x += w0; den[c].y += w1; den[c].z += w2; den[c].w += w3;
            num[c].x += m0 * w0; num[c].y += m1 * w1;
            num[c].z += m2 * w2; num[c].w += m3 * w3;
        }
    }

#pragma unroll
    for (int c = 0; c < 4; c++) {
        int gi = (c * NN + dst) * 4 + f4;
        float4 qs = q4[gi];
        float4 r;
        r.x = qs.x + ((den[c].x > 0.f) ? num[c].x / den[c].x : 0.f);
        r.y = qs.y + ((den[c].y > 0.f) ? num[c].y / den[c].y : 0.f);
        r.z = qs.z + ((den[c].z > 0.f) ? num[c].z / den[c].z : 0.f);
        r.w = qs.w + ((den[c].w > 0.f) ? num[c].w / den[c].w : 0.f);
        ((float4*)g_x)[gi] = r;
    }
}

// ---------------------------------------------------------------------------
// Kernel 4: 2-layer quaternion MLP on x. 256 threads = 4 nodes/block,
// 64 threads per node (idx = co*16 + fo).
// ---------------------------------------------------------------------------
__global__ void __launch_bounds__(256) k_mlp(const float* __restrict__ W1,
                                             const float* __restrict__ b1,
                                             const float* __restrict__ W2,
                                             const float* __restrict__ b2,
                                             float*       __restrict__ out) {
    __shared__ float w1s[1024], w2s[1024], b1s[64], b2s[64];
    __shared__ float xs[4][64], hs[4][64];

    int t = threadIdx.x;
    for (int i = t; i < 1024; i += 256) { w1s[i] = W1[i]; w2s[i] = W2[i]; }
    if (t < 64) { b1s[t] = b1[t]; b2s[t] = b2[t]; }

    int nl   = t >> 6;
    int idx  = t & 63;
    int co   = idx >> 4;
    int fo   = idx & 15;
    int node = blockIdx.x * 4 + nl;

    const int   mtab[4][4] = {{0,1,2,3},{1,0,3,2},{2,3,0,1},{3,2,1,0}};
    const float stab[4][4] = {{ 1.f,-1.f,-1.f,-1.f},
                              { 1.f, 1.f, 1.f,-1.f},
                              { 1.f,-1.f, 1.f, 1.f},
                              { 1.f, 1.f,-1.f, 1.f}};

    __syncthreads();

    if (node < NN)
        xs[nl][idx] = g_x[(co * NN + node) * FF + fo];
    __syncthreads();

    if (node < NN) {
        float h = b1s[idx];
#pragma unroll
        for (int ci = 0; ci < 4; ci++) {
            int   m = mtab[co][ci];
            float s = stab[co][ci];
            const float* wp = &w1s[m * 256 + fo];
            const float* xp = &xs[nl][ci * 16];
#pragma unroll
            for (int fi = 0; fi < 16; fi++)
                h += s * xp[fi] * wp[fi * 16];
        }
        hs[nl][idx] = fmaxf(h, 0.f);
    }
    __syncthreads();

    if (node < NN) {
        float o = b2s[idx];
#pragma unroll
        for (int ci = 0; ci < 4; ci++) {
            int   m = mtab[co][ci];
            float s = stab[co][ci];
            const float* wp = &w2s[m * 256 + fo];
            const float* hp = &hs[nl][ci * 16];
#pragma unroll
            for (int fi = 0; fi < 16; fi++)
                o += s * hp[fi] * wp[fi * 16];
        }
        out[(co * NN + node) * FF + fo] = o;
    }
}

// ---------------------------------------------------------------------------
// Launch. Inputs: q, edge_attr, edge_index, W1, b1, W2, b2, beta
// ---------------------------------------------------------------------------
extern "C" void kernel_launch(void* const* d_in, const int* in_sizes, int n_in,
                              void* d_out, int out_size) {
    const float* q    = (const float*)d_in[0];
    const float* ea   = (const float*)d_in[1];
    const int*   ei   = (const int*)  d_in[2];
    const float* W1   = (const float*)d_in[3];
    const float* b1   = (const float*)d_in[4];
    const float* W2   = (const float*)d_in[5];
    const float* b2   = (const float*)d_in[6];
    const float* beta = (const float*)d_in[7];
    float* out = (float*)d_out;

    k_zcur<<<(NN + 255) / 256, 256>>>();
    k_scatter<<<(EE + 255) / 256, 256>>>(ei);
    k_gather<<<(NN * 4 + 255) / 256, 256>>>(q, ea, ei, beta);
    k_mlp<<<(NN + 3) / 4, 256>>>(W1, b1, W2, b2, out);
}

// round 7
// speedup vs baseline: 1.4947x; 1.4947x over previous
#include <cuda_runtime.h>
#include <cuda_bf16.h>

// Problem constants
#define NN 50000
#define EE 800000
#define FF 16
#define MAXDEG 96   // Poisson(16) degrees; P(deg > 96) astronomically small

// Scratch
__device__ int g_cursor[NN];                      // per-dst edge count / cursor
__device__ int g_el[NN * MAXDEG];                 // bucketed edge ids
__device__ __align__(16) float g_x[4 * NN * FF];  // x = q + agg
__device__ __align__(16) float g_w1e[64 * 64];    // sign-folded expanded weights, [k][col]
__device__ __align__(16) float g_w2e[64 * 64];

// ---------------------------------------------------------------------------
// Kernel 1: zero the cursors (must happen every replay)
// ---------------------------------------------------------------------------
__global__ void k_zcur() {
    int i = blockIdx.x * blockDim.x + threadIdx.x;
    if (i < NN) g_cursor[i] = 0;
}

// ---------------------------------------------------------------------------
// Kernel 2: scatter edge ids into per-dst buckets. 800k int atomics only.
// ---------------------------------------------------------------------------
__global__ void __launch_bounds__(256) k_scatter(const int* __restrict__ ei) {
    int e = blockIdx.x * blockDim.x + threadIdx.x;
    if (e >= EE) return;
    int dst = ei[EE + e];
    int pos = atomicAdd(&g_cursor[dst], 1);
    if (pos < MAXDEG) g_el[dst * MAXDEG + pos] = e;
}

// ---------------------------------------------------------------------------
// Kernel 3: expand quaternion weights into dense sign-folded 64x64 matrices.
// W_e[k][col] = s(co,ci) * W[m(co,ci)][fi][fo],  k=ci*16+fi, col=co*16+fo.
// ---------------------------------------------------------------------------
__global__ void k_wexp(const float* __restrict__ W1, const float* __restrict__ W2) {
    const int   mtab[4][4] = {{0,1,2,3},{1,0,3,2},{2,3,0,1},{3,2,1,0}};
    const float stab[4][4] = {{ 1.f,-1.f,-1.f,-1.f},
                              { 1.f, 1.f, 1.f,-1.f},
                              { 1.f,-1.f, 1.f, 1.f},
                              { 1.f, 1.f,-1.f, 1.f}};
    int i = blockIdx.x * blockDim.x + threadIdx.x;   // 0..4095
    if (i >= 4096) return;
    int k   = i >> 6;
    int col = i & 63;
    int ci = k >> 4, fi = k & 15;
    int co = col >> 4, fo = col & 15;
    int   m = mtab[co][ci];
    float s = stab[co][ci];
    g_w1e[i] = s * W1[m * 256 + fi * 16 + fo];
    g_w2e[i] = s * W2[m * 256 + fi * 16 + fo];
}

// ---------------------------------------------------------------------------
// Kernel 4: atomic-free gather. Thread = (dst, f4); loops the dst's edge
// bucket with the 4 quaternion components unrolled inside. Prefetch depth 2
// hides the el->ei dependent-load latency. Softmax num/den in registers.
//   m = q[c,src,f] + ea[c,e,f];  w = exp(beta*m)   (|z| <= ~9: no max pass)
//   x[c,dst,f] = q[c,dst,f] + num/den
// ---------------------------------------------------------------------------
__global__ void __launch_bounds__(256) k_gather(const float* __restrict__ q,
                                                const float* __restrict__ ea,
                                                const int*   __restrict__ ei,
                                                const float* __restrict__ beta) {
    int tid = blockIdx.x * blockDim.x + threadIdx.x;
    if (tid >= NN * 4) return;
    int dst = tid >> 2;
    int f4  = tid & 3;

    float b = beta[0];
    int deg = g_cursor[dst];
    if (deg > MAXDEG) deg = MAXDEG;

    const float4* q4  = (const float4*)q;
    const float4* ea4 = (const float4*)ea;

    float4 num[4], den[4];
#pragma unroll
    for (int c = 0; c < 4; c++) {
        num[c] = make_float4(0.f, 0.f, 0.f, 0.f);
        den[c] = make_float4(0.f, 0.f, 0.f, 0.f);
    }

    int base = dst * MAXDEG;
    int e0 = (deg > 0) ? g_el[base]     : 0;
    int e1 = (deg > 1) ? g_el[base + 1] : 0;
    int s0 = (deg > 0) ? __ldg(&ei[e0]) : 0;
    int s1 = (deg > 1) ? __ldg(&ei[e1]) : 0;

    for (int i = 0; i < deg; i++) {
        int e   = e0;
        int src = s0;
        e0 = e1; s0 = s1;
        if (i + 2 < deg) {                       // prefetch 2 ahead
            e1 = g_el[base + i + 2];
            s1 = __ldg(&ei[e1]);
        }
#pragma unroll
        for (int c = 0; c < 4; c++) {
            float4 a  = ea4[(c * EE + e) * 4 + f4];
            float4 qs = q4[(c * NN + src) * 4 + f4];
            float m0 = a.x + qs.x, m1 = a.y + qs.y;
            float m2 = a.z + qs.z, m3 = a.w + qs.w;
            float w0 = __expf(b * m0), w1 = __expf(b * m1);
            float w2 = __expf(b * m2), w3 = __expf(b * m3);
            den[c].x += w0; den[c].y += w1; den[c].z += w2; den[c].w += w3;
            num[c].x += m0 * w0; num[c].y += m1 * w1;
            num[c].z += m2 * w2; num[c].w += m3 * w3;
        }
    }

#pragma unroll
    for (int c = 0; c < 4; c++) {
        int gi = (c * NN + dst) * 4 + f4;
        float4 qs = q4[gi];
        float4 r;
        r.x = qs.x + ((den[c].x > 0.f) ? num[c].x / den[c].x : 0.f);
        r.y = qs.y + ((den[c].y > 0.f) ? num[c].y / den[c].y : 0.f);
        r.z = qs.z + ((den[c].z > 0.f) ? num[c].z / den[c].z : 0.f);
        r.w = qs.w + ((den[c].w > 0.f) ? num[c].w / den[c].w : 0.f);
        ((float4*)g_x)[gi] = r;
    }
}

// ---------------------------------------------------------------------------
// Kernel 5: 2-layer MLP as two register-tiled 64x64 GEMMs on expanded
// weights. 256 threads, 16 nodes per block (50000 = 3125 * 16).
// Thread = (node-quad ng, col). Per k-step: 1 conflict-free scalar LDS for
// the weight + 1 broadcast float4 LDS for 4 nodes' x -> 4 FFMA.
// ---------------------------------------------------------------------------
#define XT_STRIDE 20   // row stride (floats): 80B, 16B-aligned float4 rows
__global__ void __launch_bounds__(256) k_mlp(const float* __restrict__ b1,
                                             const float* __restrict__ b2,
                                             float*       __restrict__ out) {
    __shared__ __align__(16) float w1s[4096];
    __shared__ __align__(16) float w2s[4096];
    __shared__ __align__(16) float xt[64 * XT_STRIDE];
    __shared__ __align__(16) float ht[64 * XT_STRIDE];
    __shared__ float b1s[64], b2s[64];

    int t = threadIdx.x;
    for (int i = t; i < 4096; i += 256) { w1s[i] = g_w1e[i]; w2s[i] = g_w2e[i]; }
    if (t < 64) { b1s[t] = b1[t]; b2s[t] = b2[t]; }

    int node0 = blockIdx.x * 16;

    // stage x transposed: xt[k][n], k = c*16+f
    for (int i = t; i < 1024; i += 256) {
        int n = i >> 6, k = i & 63;
        int c = k >> 4, f = k & 15;
        xt[k * XT_STRIDE + n] = g_x[(c * NN + node0 + n) * FF + f];
    }
    __syncthreads();

    int col = t & 63;
    int ng  = t >> 6;          // node quad 0..3 -> nodes ng*4 .. ng*4+3

    // ---- layer 1 ----
    float bv = b1s[col];
    float4 acc = make_float4(bv, bv, bv, bv);
#pragma unroll 8
    for (int k = 0; k < 64; k++) {
        float  w  = w1s[k * 64 + col];
        float4 xv = *(const float4*)&xt[k * XT_STRIDE + ng * 4];
        acc.x += w * xv.x; acc.y += w * xv.y;
        acc.z += w * xv.z; acc.w += w * xv.w;
    }
    // relu + transpose into ht[col][n]
    ht[col * XT_STRIDE + ng * 4 + 0] = fmaxf(acc.x, 0.f);
    ht[col * XT_STRIDE + ng * 4 + 1] = fmaxf(acc.y, 0.f);
    ht[col * XT_STRIDE + ng * 4 + 2] = fmaxf(acc.z, 0.f);
    ht[col * XT_STRIDE + ng * 4 + 3] = fmaxf(acc.w, 0.f);
    __syncthreads();

    // ---- layer 2 ----
    bv = b2s[col];
    acc = make_float4(bv, bv, bv, bv);
#pragma unroll 8
    for (int k = 0; k < 64; k++) {
        float  w  = w2s[k * 64 + col];
        float4 hv = *(const float4*)&ht[k * XT_STRIDE + ng * 4];
        acc.x += w * hv.x; acc.y += w * hv.y;
        acc.z += w * hv.z; acc.w += w * hv.w;
    }

    int co = col >> 4, fo = col & 15;
    int obase = (co * NN + node0 + ng * 4) * FF + fo;
    out[obase + 0 * FF] = acc.x;
    out[obase + 1 * FF] = acc.y;
    out[obase + 2 * FF] = acc.z;
    out[obase + 3 * FF] = acc.w;
}

// ---------------------------------------------------------------------------
// Launch. Inputs: q, edge_attr, edge_index, W1, b1, W2, b2, beta
// ---------------------------------------------------------------------------
extern "C" void kernel_launch(void* const* d_in, const int* in_sizes, int n_in,
                              void* d_out, int out_size) {
    const float* q    = (const float*)d_in[0];
    const float* ea   = (const float*)d_in[1];
    const int*   ei   = (const int*)  d_in[2];
    const float* W1   = (const float*)d_in[3];
    const float* b1   = (const float*)d_in[4];
    const float* W2   = (const float*)d_in[5];
    const float* b2   = (const float*)d_in[6];
    const float* beta = (const float*)d_in[7];
    float* out = (float*)d_out;

    k_zcur<<<(NN + 255) / 256, 256>>>();
    k_scatter<<<(EE + 255) / 256, 256>>>(ei);
    k_wexp<<<16, 256>>>(W1, W2);
    k_gather<<<(NN * 4 + 255) / 256, 256>>>(q, ea, ei, beta);
    k_mlp<<<NN / 16, 256>>>(b1, b2, out);
}